// round 1
// baseline (speedup 1.0000x reference)
#include <cuda_runtime.h>
#include <math.h>

#define SEQ 1024
#define CS  1024
#define NH  16
#define HD  64
#define CZ  128

// ---------------- scratch (device globals; no allocation allowed) -------------
__device__ float g_q[SEQ * CS];
__device__ float g_k[SEQ * CS];
__device__ float g_v[SEQ * CS];
__device__ float g_g[SEQ * CS];
__device__ float g_o[SEQ * CS];
__device__ float g_att[(size_t)NH * SEQ * SEQ];   // z -> scores -> probs (64 MB)

// ---------------- generic tiled SGEMM: C = op(A @ B(^T)) ----------------------
// TB=true : C[m,n] = sum_k A[m*lda+k] * B[n*ldb+k]   (NT, weights row-major)
// TB=false: C[m,n] = sum_k A[m*lda+k] * B[k*ldb+n]   (NN)
// mode 0: plain  1: +bias[n]  2: sigmoid  3: acc*scale + addsrc[m*ldc+n]
template <bool TB>
__global__ __launch_bounds__(256) void gemm_kernel(
    const float* __restrict__ A, int lda, long aHeadOff,
    const float* __restrict__ B, int ldb, long bHeadOff,
    float* __restrict__ C, int ldc, long cHeadOff,
    int K,
    const float* __restrict__ bias, int mode, float scale,
    const float* __restrict__ addsrc)
{
    constexpr int BM = 64, BN = 64, BK = 16;
    __shared__ float As[BK][BM + 4];
    __shared__ float Bs[BK][BN + 4];

    int h = blockIdx.z;
    A += (long)h * aHeadOff;
    B += (long)h * bHeadOff;
    C += (long)h * cHeadOff;
    if (addsrc) addsrc += (long)h * cHeadOff;

    int m0 = blockIdx.y * BM;
    int n0 = blockIdx.x * BN;
    int t  = threadIdx.x;
    int tx = t & 15;        // 0..15 -> n
    int ty = t >> 4;        // 0..15 -> m

    float acc[4][4];
#pragma unroll
    for (int i = 0; i < 4; i++)
#pragma unroll
        for (int j = 0; j < 4; j++) acc[i][j] = 0.f;

    for (int k0 = 0; k0 < K; k0 += BK) {
        {   // A tile: 64 rows x 16 k, transpose into As[k][m]
            int r = t >> 2;
            int c = (t & 3) << 2;
            float4 av = *(const float4*)&A[(long)(m0 + r) * lda + k0 + c];
            As[c + 0][r] = av.x;
            As[c + 1][r] = av.y;
            As[c + 2][r] = av.z;
            As[c + 3][r] = av.w;
        }
        if (TB) {           // B tile: 64 n-rows x 16 k, transpose into Bs[k][n]
            int r = t >> 2;
            int c = (t & 3) << 2;
            float4 bv = *(const float4*)&B[(long)(n0 + r) * ldb + k0 + c];
            Bs[c + 0][r] = bv.x;
            Bs[c + 1][r] = bv.y;
            Bs[c + 2][r] = bv.z;
            Bs[c + 3][r] = bv.w;
        } else {            // B tile: 16 k-rows x 64 n, direct
            int r = t >> 4;
            int c = (t & 15) << 2;
            float4 bv = *(const float4*)&B[(long)(k0 + r) * ldb + n0 + c];
            *(float4*)&Bs[r][c] = bv;
        }
        __syncthreads();

#pragma unroll
        for (int kk = 0; kk < BK; kk++) {
            float4 a = *(const float4*)&As[kk][ty << 2];
            float4 b = *(const float4*)&Bs[kk][tx << 2];
            acc[0][0] += a.x * b.x; acc[0][1] += a.x * b.y; acc[0][2] += a.x * b.z; acc[0][3] += a.x * b.w;
            acc[1][0] += a.y * b.x; acc[1][1] += a.y * b.y; acc[1][2] += a.y * b.z; acc[1][3] += a.y * b.w;
            acc[2][0] += a.z * b.x; acc[2][1] += a.z * b.y; acc[2][2] += a.z * b.z; acc[2][3] += a.z * b.w;
            acc[3][0] += a.w * b.x; acc[3][1] += a.w * b.y; acc[3][2] += a.w * b.z; acc[3][3] += a.w * b.w;
        }
        __syncthreads();
    }

#pragma unroll
    for (int i = 0; i < 4; i++) {
        int m = m0 + (ty << 2) + i;
#pragma unroll
        for (int j = 0; j < 4; j++) {
            int n = n0 + (tx << 2) + j;
            float val = acc[i][j];
            if (mode == 1)      val += bias[n];
            else if (mode == 2) val = 1.f / (1.f + __expf(-val));
            else if (mode == 3) val = val * scale + addsrc[(long)m * ldc + n];
            C[(long)m * ldc + n] = val;
        }
    }
}

// ---------------- z = einsum(bias[i,j,c], Wz[c,h]) + (1-mask[j])*(-INF) -------
// one block per i; each thread owns 4 j's (j = t, t+256, t+512, t+768)
__global__ __launch_bounds__(256) void zbias_kernel(
    const float* __restrict__ bias, const float* __restrict__ Wz,
    const float* __restrict__ mask, float* __restrict__ zout)
{
    __shared__ float wz[CZ * NH];
    int t = threadIdx.x;
    for (int idx = t; idx < CZ * NH; idx += 256) wz[idx] = Wz[idx];
    __syncthreads();

    int i = blockIdx.x;
    const float* bp = bias + (size_t)i * SEQ * CZ;

    float acc[4][NH];
#pragma unroll
    for (int p = 0; p < 4; p++)
#pragma unroll
        for (int h = 0; h < NH; h++) acc[p][h] = 0.f;

#pragma unroll 1
    for (int c4 = 0; c4 < CZ / 4; c4++) {
        float bvf[4][4];
#pragma unroll
        for (int p = 0; p < 4; p++) {
            float4 bv = *(const float4*)(bp + (size_t)(t + p * 256) * CZ + c4 * 4);
            bvf[p][0] = bv.x; bvf[p][1] = bv.y; bvf[p][2] = bv.z; bvf[p][3] = bv.w;
        }
#pragma unroll
        for (int cc = 0; cc < 4; cc++) {
            int c = c4 * 4 + cc;
            float4 w0 = *(const float4*)&wz[c * NH + 0];
            float4 w1 = *(const float4*)&wz[c * NH + 4];
            float4 w2 = *(const float4*)&wz[c * NH + 8];
            float4 w3 = *(const float4*)&wz[c * NH + 12];
#pragma unroll
            for (int p = 0; p < 4; p++) {
                float b = bvf[p][cc];
                acc[p][0]  += b * w0.x; acc[p][1]  += b * w0.y; acc[p][2]  += b * w0.z; acc[p][3]  += b * w0.w;
                acc[p][4]  += b * w1.x; acc[p][5]  += b * w1.y; acc[p][6]  += b * w1.z; acc[p][7]  += b * w1.w;
                acc[p][8]  += b * w2.x; acc[p][9]  += b * w2.y; acc[p][10] += b * w2.z; acc[p][11] += b * w2.w;
                acc[p][12] += b * w3.x; acc[p][13] += b * w3.y; acc[p][14] += b * w3.z; acc[p][15] += b * w3.w;
            }
        }
    }

    float mk[4];
#pragma unroll
    for (int p = 0; p < 4; p++)
        mk[p] = (1.0f - mask[t + p * 256]) * (-1000000.0f);

#pragma unroll
    for (int h = 0; h < NH; h++) {
        float* row = zout + ((size_t)h * SEQ + i) * SEQ;
#pragma unroll
        for (int p = 0; p < 4; p++)
            row[t + p * 256] = acc[p][h] + mk[p];
    }
}

// ---------------- row softmax over j (1024 per row) ---------------------------
__global__ __launch_bounds__(256) void softmax_kernel(float* __restrict__ att)
{
    __shared__ float redm[8];
    __shared__ float reds[8];
    size_t row = blockIdx.x;
    float* p = att + row * SEQ;
    int t = threadIdx.x;

    float4 v = ((float4*)p)[t];
    float m = fmaxf(fmaxf(v.x, v.y), fmaxf(v.z, v.w));
#pragma unroll
    for (int o = 16; o > 0; o >>= 1) m = fmaxf(m, __shfl_xor_sync(0xffffffffu, m, o));
    if ((t & 31) == 0) redm[t >> 5] = m;
    __syncthreads();
    if (t < 32) {
        float x = (t < 8) ? redm[t] : -1e30f;
#pragma unroll
        for (int o = 4; o > 0; o >>= 1) x = fmaxf(x, __shfl_xor_sync(0xffffffffu, x, o));
        if (t == 0) redm[0] = x;
    }
    __syncthreads();
    m = redm[0];

    v.x = __expf(v.x - m);
    v.y = __expf(v.y - m);
    v.z = __expf(v.z - m);
    v.w = __expf(v.w - m);
    float s = v.x + v.y + v.z + v.w;
#pragma unroll
    for (int o = 16; o > 0; o >>= 1) s += __shfl_xor_sync(0xffffffffu, s, o);
    if ((t & 31) == 0) reds[t >> 5] = s;
    __syncthreads();
    if (t < 32) {
        float x = (t < 8) ? reds[t] : 0.f;
#pragma unroll
        for (int o = 4; o > 0; o >>= 1) x += __shfl_xor_sync(0xffffffffu, x, o);
        if (t == 0) reds[0] = x;
    }
    __syncthreads();
    float inv = 1.0f / reds[0];

    v.x *= inv; v.y *= inv; v.z *= inv; v.w *= inv;
    ((float4*)p)[t] = v;
}

// ---------------- elementwise c = a * b  (float4) -----------------------------
__global__ __launch_bounds__(256) void mul_kernel(
    const float* __restrict__ a, const float* __restrict__ b, float* __restrict__ c)
{
    int i = blockIdx.x * blockDim.x + threadIdx.x;
    float4 av = ((const float4*)a)[i];
    float4 bv = ((const float4*)b)[i];
    float4 cv;
    cv.x = av.x * bv.x; cv.y = av.y * bv.y; cv.z = av.z * bv.z; cv.w = av.w * bv.w;
    ((float4*)c)[i] = cv;
}

// ---------------- launcher ----------------------------------------------------
extern "C" void kernel_launch(void* const* d_in, const int* in_sizes, int n_in,
                              void* d_out, int out_size)
{
    const float* s    = (const float*)d_in[0];
    const float* k_in = (const float*)d_in[1];
    const float* mask = (const float*)d_in[2];
    const float* bias = (const float*)d_in[3];
    const float* Wq   = (const float*)d_in[4];
    const float* bq   = (const float*)d_in[5];
    const float* Wk   = (const float*)d_in[6];
    const float* Wv   = (const float*)d_in[7];
    const float* Wg   = (const float*)d_in[8];
    const float* Wo   = (const float*)d_in[9];
    const float* Wz   = (const float*)d_in[10];
    float* out = (float*)d_out;

    float *pq, *pk, *pv, *pg, *po, *patt;
    cudaGetSymbolAddress((void**)&pq,   g_q);
    cudaGetSymbolAddress((void**)&pk,   g_k);
    cudaGetSymbolAddress((void**)&pv,   g_v);
    cudaGetSymbolAddress((void**)&pg,   g_g);
    cudaGetSymbolAddress((void**)&po,   g_o);
    cudaGetSymbolAddress((void**)&patt, g_att);

    dim3 blk(256);
    dim3 grid_pp(CS / 64, SEQ / 64, 1);       // 16 x 16 projections

    // QKV + gate projections (NT vs row-major weights)
    gemm_kernel<true><<<grid_pp, blk>>>(s,    CS, 0, Wq, CS, 0, pq, CS, 0, CS, bq,      1, 0.f, nullptr);
    gemm_kernel<true><<<grid_pp, blk>>>(k_in, CS, 0, Wk, CS, 0, pk, CS, 0, CS, nullptr, 0, 0.f, nullptr);
    gemm_kernel<true><<<grid_pp, blk>>>(k_in, CS, 0, Wv, CS, 0, pv, CS, 0, CS, nullptr, 0, 0.f, nullptr);
    gemm_kernel<true><<<grid_pp, blk>>>(s,    CS, 0, Wg, CS, 0, pg, CS, 0, CS, nullptr, 2, 0.f, nullptr);

    // pair bias z[h,i,j] (+ mask), reads 512 MB bias exactly once
    zbias_kernel<<<SEQ, blk>>>(bias, Wz, mask, patt);

    // scores[h,i,j] = qk / 8 + z   (per-head NT, K=64)
    dim3 grid_qk(SEQ / 64, SEQ / 64, NH);
    gemm_kernel<true><<<grid_qk, blk>>>(pq, CS, HD, pk, CS, HD,
                                        patt, SEQ, (long)SEQ * SEQ, HD,
                                        nullptr, 3, 0.125f, patt);

    // softmax over j
    softmax_kernel<<<NH * SEQ, blk>>>(patt);

    // o[i, h*64+d] = P @ V      (per-head NN, N=64, K=1024)
    dim3 grid_av(1, SEQ / 64, NH);
    gemm_kernel<false><<<grid_av, blk>>>(patt, SEQ, (long)SEQ * SEQ, pv, CS, HD,
                                         po, CS, HD, SEQ,
                                         nullptr, 0, 0.f, nullptr);

    // g * o  (into g_q scratch, q no longer needed)
    mul_kernel<<<(SEQ * CS / 4) / 256, blk>>>(pg, po, pq);

    // out = (g*o) @ Wo^T
    gemm_kernel<true><<<grid_pp, blk>>>(pq, CS, 0, Wo, CS, 0, out, CS, 0, CS,
                                        nullptr, 0, 0.f, nullptr);
}

// round 5
// speedup vs baseline: 1.3389x; 1.3389x over previous
#include <cuda_runtime.h>
#include <mma.h>
#include <math.h>

using namespace nvcuda;

#define SEQ 1024
#define CS  1024
#define NH  16
#define HD  64
#define CZ  128

// ---------------- scratch (device globals; no allocation allowed) -------------
__device__ float g_q[SEQ * CS];
__device__ float g_k[SEQ * CS];
__device__ float g_v[SEQ * CS];
__device__ float g_g[SEQ * CS];
__device__ float g_o[SEQ * CS];
__device__ float g_att[(size_t)NH * SEQ * SEQ];   // z -> scores -> probs (64 MB)

// =============================================================================
// TF32 WMMA GEMM body: 64x64 block tile, BK=32, 8 warps (warp = 16x32 of C)
// TB=true : C[m,n] = sum_k A[m*lda+k] * B[n*ldb+k]   (NT)
// TB=false: C[m,n] = sum_k A[m*lda+k] * B[k*ldb+n]   (NN)
// mode 0: plain  1: +bias[n]  2: sigmoid  3: acc*scale + addsrc[m*ldc+n]
// A2 (optional): A-element is A[i]*A2[i] (fused elementwise gate)
// =============================================================================
#define SMEM_FLOATS 4608   // max(As 64*36 + Bs 64*36, Cs 64*68)

template <bool TB>
__device__ __forceinline__ void gemm_body(
    const float* __restrict__ A, const float* __restrict__ A2, int lda,
    const float* __restrict__ B, int ldb,
    float* __restrict__ C, int ldc, int K,
    const float* __restrict__ bias, int mode, float scale,
    const float* __restrict__ addsrc, float* buf)
{
    constexpr int BK = 32;
    const int t  = threadIdx.x;
    const int m0 = blockIdx.y * 64;
    const int n0 = blockIdx.x * 64;
    const int w  = t >> 5;
    const int warp_m = w >> 1;   // 0..3
    const int warp_n = w & 1;    // 0..1

    float* As = buf;             // 64 x 36
    float* Bs = buf + 64 * 36;   // TB: 64 x 36 ; NN: 32 x 68

    wmma::fragment<wmma::accumulator, 16, 16, 8, float> acc[2];
    wmma::fill_fragment(acc[0], 0.f);
    wmma::fill_fragment(acc[1], 0.f);

    for (int k0 = 0; k0 < K; k0 += BK) {
        {   // A tile: 64 rows x 32 k (8 floats / thread)
            int r = t >> 2, c = (t & 3) << 3;
            const float* ap = A + (long)(m0 + r) * lda + k0 + c;
            float4 v0 = *(const float4*)ap;
            float4 v1 = *(const float4*)(ap + 4);
            if (A2) {
                const float* gp = A2 + (long)(m0 + r) * lda + k0 + c;
                float4 u0 = *(const float4*)gp;
                float4 u1 = *(const float4*)(gp + 4);
                v0.x *= u0.x; v0.y *= u0.y; v0.z *= u0.z; v0.w *= u0.w;
                v1.x *= u1.x; v1.y *= u1.y; v1.z *= u1.z; v1.w *= u1.w;
            }
            *(float4*)&As[r * 36 + c]     = v0;
            *(float4*)&As[r * 36 + c + 4] = v1;
        }
        if (TB) {   // B tile: 64 n-rows x 32 k
            int r = t >> 2, c = (t & 3) << 3;
            const float* bp = B + (long)(n0 + r) * ldb + k0 + c;
            *(float4*)&Bs[r * 36 + c]     = *(const float4*)bp;
            *(float4*)&Bs[r * 36 + c + 4] = *(const float4*)(bp + 4);
        } else {    // B tile: 32 k-rows x 64 n
            int r = t >> 3, c = (t & 7) << 3;
            const float* bp = B + (long)(k0 + r) * ldb + n0 + c;
            *(float4*)&Bs[r * 68 + c]     = *(const float4*)bp;
            *(float4*)&Bs[r * 68 + c + 4] = *(const float4*)(bp + 4);
        }
        __syncthreads();

#pragma unroll
        for (int kk = 0; kk < BK; kk += 8) {
            wmma::fragment<wmma::matrix_a, 16, 16, 8, wmma::precision::tf32, wmma::row_major> af;
            wmma::load_matrix_sync(af, &As[warp_m * 16 * 36 + kk], 36);
#pragma unroll
            for (int i = 0; i < af.num_elements; i++)
                af.x[i] = wmma::__float_to_tf32(af.x[i]);
#pragma unroll
            for (int j = 0; j < 2; j++) {
                int nl = warp_n * 32 + j * 16;
                if constexpr (TB) {
                    wmma::fragment<wmma::matrix_b, 16, 16, 8, wmma::precision::tf32, wmma::col_major> bf;
                    wmma::load_matrix_sync(bf, &Bs[nl * 36 + kk], 36);
#pragma unroll
                    for (int i = 0; i < bf.num_elements; i++)
                        bf.x[i] = wmma::__float_to_tf32(bf.x[i]);
                    wmma::mma_sync(acc[j], af, bf, acc[j]);
                } else {
                    wmma::fragment<wmma::matrix_b, 16, 16, 8, wmma::precision::tf32, wmma::row_major> bf;
                    wmma::load_matrix_sync(bf, &Bs[kk * 68 + nl], 68);
#pragma unroll
                    for (int i = 0; i < bf.num_elements; i++)
                        bf.x[i] = wmma::__float_to_tf32(bf.x[i]);
                    wmma::mma_sync(acc[j], af, bf, acc[j]);
                }
            }
        }
        __syncthreads();
    }

    // epilogue via smem (reuse buf as Cs 64x68)
    wmma::store_matrix_sync(&buf[warp_m * 16 * 68 + warp_n * 32],      acc[0], 68, wmma::mem_row_major);
    wmma::store_matrix_sync(&buf[warp_m * 16 * 68 + warp_n * 32 + 16], acc[1], 68, wmma::mem_row_major);
    __syncthreads();

    {
        int r = t >> 2, c0 = (t & 3) << 4;
        long crow = (long)(m0 + r) * ldc;
#pragma unroll
        for (int qd = 0; qd < 4; qd++) {
            int cl = c0 + qd * 4;
            int n  = n0 + cl;
            float4 v = *(float4*)&buf[r * 68 + cl];
            if (mode == 1) {
                const float4 b4 = *(const float4*)&bias[n];
                v.x += b4.x; v.y += b4.y; v.z += b4.z; v.w += b4.w;
            } else if (mode == 2) {
                v.x = 1.f / (1.f + __expf(-v.x));
                v.y = 1.f / (1.f + __expf(-v.y));
                v.z = 1.f / (1.f + __expf(-v.z));
                v.w = 1.f / (1.f + __expf(-v.w));
            } else if (mode == 3) {
                const float4 a4 = *(const float4*)&addsrc[crow + n];
                v.x = v.x * scale + a4.x;
                v.y = v.y * scale + a4.y;
                v.z = v.z * scale + a4.z;
                v.w = v.w * scale + a4.w;
            }
            *(float4*)&C[crow + n] = v;
        }
    }
}

// ---------------- fused 4-way projection: z picks q/k/v/g ---------------------
__global__ __launch_bounds__(256) void proj4_kernel(
    const float* __restrict__ s, const float* __restrict__ k_in,
    const float* __restrict__ Wq, const float* __restrict__ bq,
    const float* __restrict__ Wk, const float* __restrict__ Wv,
    const float* __restrict__ Wg,
    float* __restrict__ q, float* __restrict__ k,
    float* __restrict__ v, float* __restrict__ g)
{
    __shared__ float buf[SMEM_FLOATS];
    int z = blockIdx.z;
    const float* A = (z == 0 || z == 3) ? s : k_in;
    const float* W = (z == 0) ? Wq : (z == 1) ? Wk : (z == 2) ? Wv : Wg;
    float*       C = (z == 0) ? q  : (z == 1) ? k  : (z == 2) ? v  : g;
    int mode       = (z == 0) ? 1  : (z == 3) ? 2  : 0;
    gemm_body<true>(A, nullptr, CS, W, CS, C, CS, CS, bq, mode, 0.f, nullptr, buf);
}

// ---------------- generic (optionally per-head batched) GEMM wrapper ----------
template <bool TB>
__global__ __launch_bounds__(256) void gemm_wrap(
    const float* A, const float* A2, int lda, long aOff,
    const float* B, int ldb, long bOff,
    float* C, int ldc, long cOff,
    int K, const float* bias, int mode, float scale,
    const float* addsrc, long addOff)
{
    __shared__ float buf[SMEM_FLOATS];
    long h = blockIdx.z;
    gemm_body<TB>(A + h * aOff, A2, lda, B + h * bOff, ldb,
                  C + h * cOff, ldc, K, bias, mode, scale,
                  addsrc ? addsrc + h * addOff : nullptr, buf);
}

// ---------------- z = einsum(bias[i,j,c], Wz[c,h]) + (1-mask[j])*(-INF) -------
__global__ __launch_bounds__(256) void zbias_kernel(
    const float* __restrict__ bias, const float* __restrict__ Wz,
    const float* __restrict__ mask, float* __restrict__ zout)
{
    __shared__ float wz[CZ * NH];
    int t = threadIdx.x;
    for (int idx = t; idx < CZ * NH; idx += 256) wz[idx] = Wz[idx];
    __syncthreads();

    int i = blockIdx.x;
    const float* bp = bias + (size_t)i * SEQ * CZ;

    float acc[4][NH];
#pragma unroll
    for (int p = 0; p < 4; p++)
#pragma unroll
        for (int h = 0; h < NH; h++) acc[p][h] = 0.f;

#pragma unroll 1
    for (int c4 = 0; c4 < CZ / 4; c4++) {
        float bvf[4][4];
#pragma unroll
        for (int p = 0; p < 4; p++) {
            float4 bv = *(const float4*)(bp + (size_t)(t + p * 256) * CZ + c4 * 4);
            bvf[p][0] = bv.x; bvf[p][1] = bv.y; bvf[p][2] = bv.z; bvf[p][3] = bv.w;
        }
#pragma unroll
        for (int cc = 0; cc < 4; cc++) {
            int c = c4 * 4 + cc;
            float4 w0 = *(const float4*)&wz[c * NH + 0];
            float4 w1 = *(const float4*)&wz[c * NH + 4];
            float4 w2 = *(const float4*)&wz[c * NH + 8];
            float4 w3 = *(const float4*)&wz[c * NH + 12];
#pragma unroll
            for (int p = 0; p < 4; p++) {
                float b = bvf[p][cc];
                acc[p][0]  += b * w0.x; acc[p][1]  += b * w0.y; acc[p][2]  += b * w0.z; acc[p][3]  += b * w0.w;
                acc[p][4]  += b * w1.x; acc[p][5]  += b * w1.y; acc[p][6]  += b * w1.z; acc[p][7]  += b * w1.w;
                acc[p][8]  += b * w2.x; acc[p][9]  += b * w2.y; acc[p][10] += b * w2.z; acc[p][11] += b * w2.w;
                acc[p][12] += b * w3.x; acc[p][13] += b * w3.y; acc[p][14] += b * w3.z; acc[p][15] += b * w3.w;
            }
        }
    }

    float mk[4];
#pragma unroll
    for (int p = 0; p < 4; p++)
        mk[p] = (1.0f - mask[t + p * 256]) * (-1000000.0f);

#pragma unroll
    for (int h = 0; h < NH; h++) {
        float* row = zout + ((size_t)h * SEQ + i) * SEQ;
#pragma unroll
        for (int p = 0; p < 4; p++)
            row[t + p * 256] = acc[p][h] + mk[p];
    }
}

// ---------------- row softmax over j (1024 per row) ---------------------------
__global__ __launch_bounds__(256) void softmax_kernel(float* __restrict__ att)
{
    __shared__ float redm[8];
    __shared__ float reds[8];
    size_t row = blockIdx.x;
    float* p = att + row * SEQ;
    int t = threadIdx.x;

    float4 v = ((float4*)p)[t];
    float m = fmaxf(fmaxf(v.x, v.y), fmaxf(v.z, v.w));
#pragma unroll
    for (int o = 16; o > 0; o >>= 1) m = fmaxf(m, __shfl_xor_sync(0xffffffffu, m, o));
    if ((t & 31) == 0) redm[t >> 5] = m;
    __syncthreads();
    if (t < 32) {
        float x = (t < 8) ? redm[t] : -1e30f;
#pragma unroll
        for (int o = 4; o > 0; o >>= 1) x = fmaxf(x, __shfl_xor_sync(0xffffffffu, x, o));
        if (t == 0) redm[0] = x;
    }
    __syncthreads();
    m = redm[0];

    v.x = __expf(v.x - m);
    v.y = __expf(v.y - m);
    v.z = __expf(v.z - m);
    v.w = __expf(v.w - m);
    float s = v.x + v.y + v.z + v.w;
#pragma unroll
    for (int o = 16; o > 0; o >>= 1) s += __shfl_xor_sync(0xffffffffu, s, o);
    if ((t & 31) == 0) reds[t >> 5] = s;
    __syncthreads();
    if (t < 32) {
        float x = (t < 8) ? reds[t] : 0.f;
#pragma unroll
        for (int o = 4; o > 0; o >>= 1) x += __shfl_xor_sync(0xffffffffu, x, o);
        if (t == 0) reds[0] = x;
    }
    __syncthreads();
    float inv = 1.0f / reds[0];

    v.x *= inv; v.y *= inv; v.z *= inv; v.w *= inv;
    ((float4*)p)[t] = v;
}

// ---------------- launcher ----------------------------------------------------
extern "C" void kernel_launch(void* const* d_in, const int* in_sizes, int n_in,
                              void* d_out, int out_size)
{
    const float* s    = (const float*)d_in[0];
    const float* k_in = (const float*)d_in[1];
    const float* mask = (const float*)d_in[2];
    const float* bias = (const float*)d_in[3];
    const float* Wq   = (const float*)d_in[4];
    const float* bq   = (const float*)d_in[5];
    const float* Wk   = (const float*)d_in[6];
    const float* Wv   = (const float*)d_in[7];
    const float* Wg   = (const float*)d_in[8];
    const float* Wo   = (const float*)d_in[9];
    const float* Wz   = (const float*)d_in[10];
    float* out = (float*)d_out;

    float *pq, *pk, *pv, *pg, *po, *patt;
    cudaGetSymbolAddress((void**)&pq,   g_q);
    cudaGetSymbolAddress((void**)&pk,   g_k);
    cudaGetSymbolAddress((void**)&pv,   g_v);
    cudaGetSymbolAddress((void**)&pg,   g_g);
    cudaGetSymbolAddress((void**)&po,   g_o);
    cudaGetSymbolAddress((void**)&patt, g_att);

    dim3 blk(256);

    // q,k,v,g projections in one launch (tensor-core tf32)
    proj4_kernel<<<dim3(CS / 64, SEQ / 64, 4), blk>>>(
        s, k_in, Wq, bq, Wk, Wv, Wg, pq, pk, pv, pg);

    // pair bias z[h,i,j] (+ mask), reads 512 MB bias exactly once
    zbias_kernel<<<SEQ, blk>>>(bias, Wz, mask, patt);

    // scores[h,i,j] = q.kT / 8 + z   (per-head NT, K=64)
    gemm_wrap<true><<<dim3(SEQ / 64, SEQ / 64, NH), blk>>>(
        pq, nullptr, CS, HD, pk, CS, HD,
        patt, SEQ, (long)SEQ * SEQ, HD,
        nullptr, 3, 0.125f, patt, (long)SEQ * SEQ);

    // softmax over j
    softmax_kernel<<<NH * SEQ, blk>>>(patt);

    // o[i, h*64+d] = P @ V    (per-head NN, N=64, K=1024)
    gemm_wrap<false><<<dim3(1, SEQ / 64, NH), blk>>>(
        patt, nullptr, SEQ, (long)SEQ * SEQ, pv, CS, HD,
        po, CS, HD, SEQ,
        nullptr, 0, 0.f, nullptr, 0);

    // out = (g .* o) @ Wo^T  (gate fused into A-tile load)
    gemm_wrap<true><<<dim3(CS / 64, SEQ / 64, 1), blk>>>(
        po, pg, CS, 0, Wo, CS, 0,
        out, CS, 0, CS,
        nullptr, 0, 0.f, nullptr, 0);
}